// round 11
// baseline (speedup 1.0000x reference)
#include <cuda_runtime.h>
#include <cuda_fp8.h>
#include <cuda_bf16.h>

#define S_N     32
#define NHEAD   32
#define HDIM    128
#define NKVH    8
#define GQ      4
#define BSZ     16
#define MBLK    128
#define NSPLIT  16
#define CHUNK   128
#define TILE    32
#define ROWB    136          // bf16 elems per K conv row (272B: 16B-aligned, conflict-free)
#define ROWF    132          // f32 elems per V row (528B: 16B-aligned, conflict-free)
#define ATTN_SCALE 0.08838834764831845f
#define NEG_BIG   -3.402823466e38f

// dynamic smem layout (bytes)
#define OFF_RAWK  0
#define OFF_KT    (OFF_RAWK + TILE * HDIM * 4)             // 16384
#define OFF_VTF   (OFF_KT + TILE * ROWB * 2)               // +8704
#define OFF_QS    (OFF_VTF + TILE * ROWF * 4)              // +16896
#define OFF_PS    (OFF_QS + GQ * HDIM * 4)                 // +2048
#define OFF_LAST  (OFF_PS + GQ * TILE * 4)                 // +512
#define SMEM_BYTES (OFF_LAST + 16)                         // ~44.6 KB

// split-KV partial scratch (static device memory: allocation-free)
__device__ float g_po[S_N][NKVH][NSPLIT][GQ][HDIM];
__device__ float g_pm[S_N][NKVH][NSPLIT][GQ];
__device__ float g_pl[S_N][NKVH][NSPLIT][GQ];
__device__ int   g_cnt[S_N][NKVH];   // zero-init; protocol restores 0 every run

__device__ __forceinline__ void cp16(void* dst_smem, const void* src) {
    unsigned d = (unsigned)__cvta_generic_to_shared(dst_smem);
    asm volatile("cp.async.cg.shared.global [%0], [%1], 16;" :: "r"(d), "l"(src));
}
#define CP_COMMIT() asm volatile("cp.async.commit_group;" ::: "memory")
#define CP_WAIT0()  asm volatile("cp.async.wait_group 0;" ::: "memory")

// Exact emulation of reference dequant chain -> two packed bf16x2 words
__device__ __forceinline__ uint2 dq4_bf(float4 c, float s) {
    float2 a = make_float2(c.x, c.y);
    float2 b = make_float2(c.z, c.w);
    __nv_fp8x2_storage_t p0 = __nv_cvt_float2_to_fp8x2(a, __NV_SATFINITE, __NV_E4M3);
    __nv_fp8x2_storage_t p1 = __nv_cvt_float2_to_fp8x2(b, __NV_SATFINITE, __NV_E4M3);
    __half2_raw h0 = __nv_cvt_fp8x2_to_halfraw2(p0, __NV_E4M3);
    __half2_raw h1 = __nv_cvt_fp8x2_to_halfraw2(p1, __NV_E4M3);
    float2 f0 = __half22float2(*reinterpret_cast<__half2*>(&h0));
    float2 f1 = __half22float2(*reinterpret_cast<__half2*>(&h1));
    f0.x *= s; f0.y *= s; f1.x *= s; f1.y *= s;
    __nv_bfloat162 bb0 = __float22bfloat162_rn(f0);
    __nv_bfloat162 bb1 = __float22bfloat162_rn(f1);
    uint2 r;
    r.x = *reinterpret_cast<unsigned*>(&bb0);
    r.y = *reinterpret_cast<unsigned*>(&bb1);
    return r;
}
// Same chain widened to f32 (exact bf16 values) — for the in-place V tile
__device__ __forceinline__ float4 dq4_f32(float4 c, float s) {
    uint2 u = dq4_bf(c, s);
    float4 r;
    r.x = __uint_as_float(u.x << 16);
    r.y = __uint_as_float(u.x & 0xFFFF0000u);
    r.z = __uint_as_float(u.y << 16);
    r.w = __uint_as_float(u.y & 0xFFFF0000u);
    return r;
}
// bf16x2 word -> two exact f32
__device__ __forceinline__ float bflo(unsigned u) { return __uint_as_float(u << 16); }
__device__ __forceinline__ float bfhi(unsigned u) { return __uint_as_float(u & 0xFFFF0000u); }

__global__ void __launch_bounds__(128)
attn_fused_kernel(const float* __restrict__ q, const float* __restrict__ knew,
                  const float* __restrict__ vnew, const float* __restrict__ kcache,
                  const float* __restrict__ vcache, const float* __restrict__ kscale_p,
                  const float* __restrict__ vscale_p, const int* __restrict__ btab,
                  const int* __restrict__ clen, float* __restrict__ out)
{
    extern __shared__ char smem[];
    float*          rawK = (float*)(smem + OFF_RAWK);          // [TILE][HDIM] f32
    unsigned short* kt   = (unsigned short*)(smem + OFF_KT);   // [TILE][ROWB] bf16
    float*          vtf  = (float*)(smem + OFF_VTF);           // [TILE][ROWF] f32 (in-place)
    float*          qs   = (float*)(smem + OFF_QS);            // [GQ*HDIM]
    float*          ps   = (float*)(smem + OFF_PS);            // [GQ][TILE]
    int*            s_last = (int*)(smem + OFF_LAST);

    const int split = blockIdx.x;
    const int h     = blockIdx.y;
    const int s     = blockIdx.z;
    const int ctx   = clen[s];
    const int c0    = split * CHUNK;
    const int nsp   = (ctx + CHUNK - 1) / CHUNK;   // active splits for this seq
    if (split >= nsp) return;
    const int nvalid = min(CHUNK, ctx - c0);
    const int ntile  = (nvalid + TILE - 1) / TILE;

    const int t = threadIdx.x;
    const int w = t >> 5;     // warp = query head within GQA group
    const int l = t & 31;     // lane

    // stage Q (512 floats, raw f32 as in reference)
    ((float4*)qs)[t] = ((const float4*)(q + (size_t)s * (NHEAD * HDIM)
                                          + (size_t)h * (GQ * HDIM)))[t];
    const float ks = kscale_p[h];
    const float vs = vscale_p[h];
    const float* kp = knew + (size_t)s * (NKVH * HDIM) + h * HDIM + l * 4;
    const float* vp = vnew + (size_t)s * (NKVH * HDIM) + h * HDIM + l * 4;

    // hoist the chunk's 8 cache-block indices (independent LDGs, once per CTA)
    int blkArr[CHUNK / BSZ];
    #pragma unroll
    for (int j = 0; j < CHUNK / BSZ; ++j)
        blkArr[j] = btab[s * MBLK + (c0 >> 4) + j];

    // issue one tile's raw K/V into smem via cp.async (32-bit offsets: max 67M elems)
    auto issue_tile = [&](int tb) {
        #pragma unroll
        for (int i = 0; i < 8; ++i) {
            const int pl = i * 4 + w;          // tile-local position 0..31
            const int P  = (tb << 5) + pl + (c0 & 31);  // local within chunk not needed; use abs
            const unsigned Pa = (unsigned)(c0 + (tb << 5) + pl);
            const unsigned roff = (((unsigned)blkArr[tb * 2 + (pl >> 4)] * BSZ
                                    + (Pa & 15u)) * (NKVH * HDIM)) + h * HDIM + l * 4;
            cp16(&rawK[pl * HDIM + l * 4], kcache + roff);
            cp16(&vtf[pl * ROWF + l * 4], vcache + roff);
            (void)P;
        }
        CP_COMMIT();
    };

    // dq-convert: K raw f32 -> bf16 tile; V in place (same float4, no aliasing)
    auto convert_tile = [&](int tb) {
        const int base = c0 + (tb << 5);
        #pragma unroll
        for (int i = 0; i < 8; ++i) {
            const int pl = i * 4 + w;
            float4 kv = *(const float4*)&rawK[pl * HDIM + l * 4];
            float4 vv = *(const float4*)&vtf[pl * ROWF + l * 4];
            if (base + pl == ctx - 1) {  // new token: reference scatters fp8(x/scale) here
                float4 kn4 = *(const float4*)kp;
                float4 vn4 = *(const float4*)vp;
                kv = make_float4(__fdiv_rn(kn4.x, ks), __fdiv_rn(kn4.y, ks),
                                 __fdiv_rn(kn4.z, ks), __fdiv_rn(kn4.w, ks));
                vv = make_float4(__fdiv_rn(vn4.x, vs), __fdiv_rn(vn4.y, vs),
                                 __fdiv_rn(vn4.z, vs), __fdiv_rn(vn4.w, vs));
            }
            *(uint2*)&kt[pl * ROWB + l * 4]  = dq4_bf(kv, ks);
            *(float4*)&vtf[pl * ROWF + l * 4] = dq4_f32(vv, vs);
        }
    };

    float  m    = NEG_BIG;
    float  lsum = 0.f;
    float4 o    = make_float4(0.f, 0.f, 0.f, 0.f);

    // prologue: stage tile 0
    issue_tile(0);
    CP_WAIT0();
    __syncthreads();
    convert_tile(0);
    __syncthreads();

    for (int tb = 0; tb < ntile; ++tb) {
        const int base = c0 + (tb << 5);
        const bool more = (tb + 1 < ntile);

        // V tile tb already final in vtf; raw K already converted into kt.
        // overlap: next tile's gmem->smem copies fly while we compute this tile.
        // NOTE: rawK is single-buffered; safe because convert(tb) finished before
        // issue(tb+1) starts (convert is fenced by the __syncthreads above/below),
        // and vtf writes for tb+1 land only after CP_WAIT0+sync below.
        // -- wait: vtf IS the live V tile for tb. cp.async for tb+1 would overwrite!
        // So V for tb+1 must go AFTER PV(tb). K raw is free now -> split issue:
        if (more) {  // K half can fly during compute
            #pragma unroll
            for (int i = 0; i < 8; ++i) {
                const int pl = i * 4 + w;
                const unsigned Pa = (unsigned)(base + TILE + pl);
                const unsigned roff = (((unsigned)blkArr[(tb + 1) * 2 + (pl >> 4)] * BSZ
                                        + (Pa & 15u)) * (NKVH * HDIM)) + h * HDIM + l * 4;
                cp16(&rawK[pl * HDIM + l * 4], kcache + roff);
            }
            CP_COMMIT();
        }

        // ---- scores: warp w = head w, lane l = position l (row l of K, 8 bf16 per LDS.128)
        float4 acc = make_float4(0.f, 0.f, 0.f, 0.f);
        #pragma unroll
        for (int d8 = 0; d8 < 16; ++d8) {
            const uint4  kq = *(const uint4*)&kt[l * ROWB + d8 * 8];
            const float4 qa = *(const float4*)&qs[w * HDIM + d8 * 8];
            const float4 qb = *(const float4*)&qs[w * HDIM + d8 * 8 + 4];
            acc.x += bflo(kq.x) * qa.x; acc.y += bfhi(kq.x) * qa.y;
            acc.z += bflo(kq.y) * qa.z; acc.w += bfhi(kq.y) * qa.w;
            acc.x += bflo(kq.z) * qb.x; acc.y += bfhi(kq.z) * qb.y;
            acc.z += bflo(kq.w) * qb.z; acc.w += bfhi(kq.w) * qb.w;
        }
        float sc = ((acc.x + acc.y) + (acc.z + acc.w)) * ATTN_SCALE;
        if (base + l >= ctx) sc = NEG_BIG;

        // online softmax (per warp)
        float tm = sc;
        #pragma unroll
        for (int off = 16; off > 0; off >>= 1)
            tm = fmaxf(tm, __shfl_xor_sync(0xFFFFFFFFu, tm, off));
        const float mnew  = fmaxf(m, tm);
        const float alpha = __expf(m - mnew);
        const float p     = __expf(sc - mnew);   // masked lanes underflow to 0
        float tsum = p;
        #pragma unroll
        for (int off = 16; off > 0; off >>= 1)
            tsum += __shfl_xor_sync(0xFFFFFFFFu, tsum, off);
        lsum = lsum * alpha + tsum;
        m = mnew;

        // ---- publish weights to smem (per-warp-private row), read as broadcast LDS.128
        __syncwarp();
        ps[w * TILE + l] = p;
        __syncwarp();

        // ---- accumulate O: lane l owns dims 4l..4l+3; V is f32, no unpacks
        o.x *= alpha; o.y *= alpha; o.z *= alpha; o.w *= alpha;
        #pragma unroll
        for (int j = 0; j < 8; ++j) {
            const float4 pw = *(const float4*)&ps[w * TILE + j * 4];
            const float4 v0 = *(const float4*)&vtf[(j * 4 + 0) * ROWF + l * 4];
            const float4 v1 = *(const float4*)&vtf[(j * 4 + 1) * ROWF + l * 4];
            const float4 v2 = *(const float4*)&vtf[(j * 4 + 2) * ROWF + l * 4];
            const float4 v3 = *(const float4*)&vtf[(j * 4 + 3) * ROWF + l * 4];
            o.x += pw.x * v0.x; o.y += pw.x * v0.y; o.z += pw.x * v0.z; o.w += pw.x * v0.w;
            o.x += pw.y * v1.x; o.y += pw.y * v1.y; o.z += pw.y * v1.z; o.w += pw.y * v1.w;
            o.x += pw.z * v2.x; o.y += pw.z * v2.y; o.z += pw.z * v2.z; o.w += pw.z * v2.w;
            o.x += pw.w * v3.x; o.y += pw.w * v3.y; o.z += pw.w * v3.z; o.w += pw.w * v3.w;
        }
        __syncthreads();   // all warps done reading kt/vtf of tile tb

        if (more) {
            // now vtf is free: issue V copies for tile tb+1 (K already in flight)
            #pragma unroll
            for (int i = 0; i < 8; ++i) {
                const int pl = i * 4 + w;
                const unsigned Pa = (unsigned)(base + TILE + pl);
                const unsigned roff = (((unsigned)blkArr[(tb + 1) * 2 + (pl >> 4)] * BSZ
                                        + (Pa & 15u)) * (NKVH * HDIM)) + h * HDIM + l * 4;
                cp16(&vtf[pl * ROWF + l * 4], vcache + roff);
            }
            CP_COMMIT();
            CP_WAIT0();        // K (long in flight) + V copies landed
            __syncthreads();
            convert_tile(tb + 1);
            __syncthreads();
        }
    }

    // ---- publish partials
    *(float4*)&g_po[s][h][split][w][l * 4] = o;
    if (l == 0) { g_pm[s][h][split][w] = m; g_pl[s][h][split][w] = lsum; }
    __threadfence();
    __syncthreads();

    // ---- last-CTA-per-(s,h) detection (threadFenceReduction pattern)
    if (t == 0) {
        const int old = atomicAdd(&g_cnt[s][h], 1);
        int last = (old == nsp - 1);
        if (last) g_cnt[s][h] = 0;     // restore for next graph replay (deterministic)
        *s_last = last;
    }
    __syncthreads();
    if (!*s_last) return;
    __threadfence();

    // ---- in-place combine for this (s,h): warp w = GQA sub-head, L2-resident reads
    const float mi = (l < nsp) ? g_pm[s][h][l][w] : NEG_BIG;
    const float li = (l < nsp) ? g_pl[s][h][l][w] : 0.f;
    float M = mi;
    #pragma unroll
    for (int off = 16; off > 0; off >>= 1)
        M = fmaxf(M, __shfl_xor_sync(0xFFFFFFFFu, M, off));
    const float wi = __expf(mi - M);     // 0 for inactive lanes
    float L = wi * li;
    #pragma unroll
    for (int off = 16; off > 0; off >>= 1)
        L += __shfl_xor_sync(0xFFFFFFFFu, L, off);

    float4 acc = make_float4(0.f, 0.f, 0.f, 0.f);
    #pragma unroll
    for (int i = 0; i < NSPLIT; ++i) {
        if (i < nsp) {
            const float wgt = __shfl_sync(0xFFFFFFFFu, wi, i);
            const float4 pv = *(const float4*)&g_po[s][h][i][w][l * 4];
            acc.x += wgt * pv.x; acc.y += wgt * pv.y;
            acc.z += wgt * pv.z; acc.w += wgt * pv.w;
        }
    }
    const float inv = 1.f / L;
    float4 r = make_float4(acc.x * inv, acc.y * inv, acc.z * inv, acc.w * inv);
    *(float4*)(out + (size_t)s * (NHEAD * HDIM)
                   + (size_t)(h * GQ + w) * HDIM + l * 4) = r;
}

extern "C" void kernel_launch(void* const* d_in, const int* in_sizes, int n_in,
                              void* d_out, int out_size) {
    (void)in_sizes; (void)n_in; (void)out_size;
    const float* q    = (const float*)d_in[0];
    const float* k    = (const float*)d_in[1];
    const float* v    = (const float*)d_in[2];
    const float* kc   = (const float*)d_in[3];
    const float* vc   = (const float*)d_in[4];
    const float* ksc  = (const float*)d_in[5];
    const float* vsc  = (const float*)d_in[6];
    // d_in[7] slot_mapping: unused (position ctx-1 substitution is equivalent)
    const int*   btab = (const int*)d_in[8];   // JAX x64 disabled -> int32
    const int*   clen = (const int*)d_in[9];

    cudaFuncSetAttribute(attn_fused_kernel,
                         cudaFuncAttributeMaxDynamicSharedMemorySize, SMEM_BYTES);
    dim3 g1(NSPLIT, NKVH, S_N);
    attn_fused_kernel<<<g1, 128, SMEM_BYTES>>>(q, k, v, kc, vc, ksc, vsc,
                                               btab, clen, (float*)d_out);
}

// round 12
// speedup vs baseline: 1.1600x; 1.1600x over previous
#include <cuda_runtime.h>
#include <cuda_fp8.h>
#include <cuda_bf16.h>

#define S_N     32
#define NHEAD   32
#define HDIM    128
#define NKVH    8
#define GQ      4
#define BSZ     16
#define MBLK    128
#define NSPLIT  16
#define CHUNK   128
#define TILE    32
#define ROWB    136          // bf16 elems per conv smem row (272B = 16B-aligned, conflict-free)
#define ATTN_SCALE 0.08838834764831845f
#define NEG_BIG   -3.402823466e38f

// dynamic smem layout (bytes)
#define OFF_RAWK  0
#define OFF_RAWV  (TILE * HDIM * 4)                        // 16384
#define OFF_KT    (OFF_RAWV + TILE * HDIM * 4)             // 32768
#define OFF_VT    (OFF_KT + TILE * ROWB * 2)               // +8704
#define OFF_QS    (OFF_VT + TILE * ROWB * 2)               // +8704
#define OFF_PS    (OFF_QS + GQ * HDIM * 4)                 // +2048
#define OFF_LAST  (OFF_PS + GQ * TILE * 4)                 // +512
#define SMEM_BYTES (OFF_LAST + 16)                         // ~52.7 KB

// split-KV partial scratch (static device memory: allocation-free)
__device__ float g_po[S_N][NKVH][NSPLIT][GQ][HDIM];
__device__ float g_pm[S_N][NKVH][NSPLIT][GQ];
__device__ float g_pl[S_N][NKVH][NSPLIT][GQ];
__device__ int   g_cnt[S_N][NKVH];   // zero-init; protocol restores 0 every run

__device__ __forceinline__ void cp16(void* dst_smem, const void* src) {
    unsigned d = (unsigned)__cvta_generic_to_shared(dst_smem);
    asm volatile("cp.async.cg.shared.global [%0], [%1], 16;" :: "r"(d), "l"(src));
}
#define CP_COMMIT() asm volatile("cp.async.commit_group;" ::: "memory")
#define CP_WAIT0()  asm volatile("cp.async.wait_group 0;" ::: "memory")

// Exact emulation of reference dequant chain -> two packed bf16x2 words
__device__ __forceinline__ uint2 dq4_bf(float4 c, float s) {
    float2 a = make_float2(c.x, c.y);
    float2 b = make_float2(c.z, c.w);
    __nv_fp8x2_storage_t p0 = __nv_cvt_float2_to_fp8x2(a, __NV_SATFINITE, __NV_E4M3);
    __nv_fp8x2_storage_t p1 = __nv_cvt_float2_to_fp8x2(b, __NV_SATFINITE, __NV_E4M3);
    __half2_raw h0 = __nv_cvt_fp8x2_to_halfraw2(p0, __NV_E4M3);
    __half2_raw h1 = __nv_cvt_fp8x2_to_halfraw2(p1, __NV_E4M3);
    float2 f0 = __half22float2(*reinterpret_cast<__half2*>(&h0));
    float2 f1 = __half22float2(*reinterpret_cast<__half2*>(&h1));
    f0.x *= s; f0.y *= s; f1.x *= s; f1.y *= s;
    __nv_bfloat162 bb0 = __float22bfloat162_rn(f0);
    __nv_bfloat162 bb1 = __float22bfloat162_rn(f1);
    uint2 r;
    r.x = *reinterpret_cast<unsigned*>(&bb0);
    r.y = *reinterpret_cast<unsigned*>(&bb1);
    return r;
}

// bf16x2 word -> two exact f32 (bf16 value = upper 16 bits of f32)
__device__ __forceinline__ float bflo(unsigned u) { return __uint_as_float(u << 16); }
__device__ __forceinline__ float bfhi(unsigned u) { return __uint_as_float(u & 0xFFFF0000u); }

__global__ void __launch_bounds__(128)
attn_fused_kernel(const float* __restrict__ q, const float* __restrict__ knew,
                  const float* __restrict__ vnew, const float* __restrict__ kcache,
                  const float* __restrict__ vcache, const float* __restrict__ kscale_p,
                  const float* __restrict__ vscale_p, const int* __restrict__ btab,
                  const int* __restrict__ clen, float* __restrict__ out)
{
    extern __shared__ char smem[];
    float*          rawK = (float*)(smem + OFF_RAWK);          // [TILE][HDIM] f32
    float*          rawV = (float*)(smem + OFF_RAWV);
    unsigned short* kt   = (unsigned short*)(smem + OFF_KT);   // [TILE][ROWB] bf16
    unsigned short* vt   = (unsigned short*)(smem + OFF_VT);
    float*          qs   = (float*)(smem + OFF_QS);            // [GQ*HDIM]
    float*          ps   = (float*)(smem + OFF_PS);            // [GQ][TILE]
    int*            s_last = (int*)(smem + OFF_LAST);

    const int split = blockIdx.x;
    const int h     = blockIdx.y;
    const int s     = blockIdx.z;
    const int ctx   = clen[s];
    const int c0    = split * CHUNK;
    const int nsp   = (ctx + CHUNK - 1) / CHUNK;   // active splits for this seq
    if (split >= nsp) return;
    const int nvalid = min(CHUNK, ctx - c0);
    const int ntile  = (nvalid + TILE - 1) / TILE;

    const int t = threadIdx.x;
    const int w = t >> 5;     // warp = query head within GQA group
    const int l = t & 31;     // lane

    // stage Q (512 floats, raw f32 as in reference)
    ((float4*)qs)[t] = ((const float4*)(q + (size_t)s * (NHEAD * HDIM)
                                          + (size_t)h * (GQ * HDIM)))[t];
    const float ks = kscale_p[h];
    const float vs = vscale_p[h];
    const float* kp = knew + (size_t)s * (NKVH * HDIM) + h * HDIM + l * 4;
    const float* vp = vnew + (size_t)s * (NKVH * HDIM) + h * HDIM + l * 4;

    // hoist the chunk's 8 cache-block indices (independent LDGs, once per CTA)
    unsigned blkArr[CHUNK / BSZ];
    #pragma unroll
    for (int j = 0; j < CHUNK / BSZ; ++j)
        blkArr[j] = (unsigned)btab[s * MBLK + (c0 >> 4) + j];

    // issue one tile's raw K/V into smem via cp.async (32-bit offsets: max 67M elems)
    auto issue_tile = [&](int tb) {
        const unsigned base = (unsigned)(c0 + (tb << 5));
        #pragma unroll
        for (int i = 0; i < 8; ++i) {
            const int pl = i * 4 + w;          // tile-local position 0..31
            const unsigned Pa = base + (unsigned)pl;   // global position (< 2048: safe)
            const unsigned roff = (blkArr[tb * 2 + (pl >> 4)] * BSZ + (Pa & 15u))
                                  * (unsigned)(NKVH * HDIM) + (unsigned)(h * HDIM + l * 4);
            cp16(&rawK[pl * HDIM + l * 4], kcache + roff);
            cp16(&rawV[pl * HDIM + l * 4], vcache + roff);
        }
        CP_COMMIT();
    };

    // dq-convert raw f32 tile -> bf16 conv tiles. Reads ONLY the rows this same
    // thread cp.async'd (same pl, same l*4) => thread-local CP_WAIT0 suffices.
    auto convert_tile = [&](int tb) {
        const int base = c0 + (tb << 5);
        #pragma unroll
        for (int i = 0; i < 8; ++i) {
            const int pl = i * 4 + w;
            float4 kv = *(const float4*)&rawK[pl * HDIM + l * 4];
            float4 vv = *(const float4*)&rawV[pl * HDIM + l * 4];
            if (base + pl == ctx - 1) {  // new token: reference scatters fp8(x/scale) here
                float4 kn4 = *(const float4*)kp;
                float4 vn4 = *(const float4*)vp;
                kv = make_float4(__fdiv_rn(kn4.x, ks), __fdiv_rn(kn4.y, ks),
                                 __fdiv_rn(kn4.z, ks), __fdiv_rn(kn4.w, ks));
                vv = make_float4(__fdiv_rn(vn4.x, vs), __fdiv_rn(vn4.y, vs),
                                 __fdiv_rn(vn4.z, vs), __fdiv_rn(vn4.w, vs));
            }
            *(uint2*)&kt[pl * ROWB + l * 4] = dq4_bf(kv, ks);
            *(uint2*)&vt[pl * ROWB + l * 4] = dq4_bf(vv, vs);
        }
    };

    float  m    = NEG_BIG;
    float  lsum = 0.f;
    float4 o    = make_float4(0.f, 0.f, 0.f, 0.f);

    // prologue: stage tile 0
    issue_tile(0);
    CP_WAIT0();
    convert_tile(0);
    __syncthreads();

    for (int tb = 0; tb < ntile; ++tb) {
        const int base = c0 + (tb << 5);
        const bool more = (tb + 1 < ntile);

        // overlap: next tile's gmem->smem copies fly while we compute this tile
        if (more) issue_tile(tb + 1);

        // ---- scores: warp w = head w, lane l = position l (row l of K, 8 bf16 per LDS.128)
        float4 acc = make_float4(0.f, 0.f, 0.f, 0.f);
        #pragma unroll
        for (int d8 = 0; d8 < 16; ++d8) {
            const uint4  kq = *(const uint4*)&kt[l * ROWB + d8 * 8];
            const float4 qa = *(const float4*)&qs[w * HDIM + d8 * 8];
            const float4 qb = *(const float4*)&qs[w * HDIM + d8 * 8 + 4];
            acc.x += bflo(kq.x) * qa.x; acc.y += bfhi(kq.x) * qa.y;
            acc.z += bflo(kq.y) * qa.z; acc.w += bfhi(kq.y) * qa.w;
            acc.x += bflo(kq.z) * qb.x; acc.y += bfhi(kq.z) * qb.y;
            acc.z += bflo(kq.w) * qb.z; acc.w += bfhi(kq.w) * qb.w;
        }
        float sc = ((acc.x + acc.y) + (acc.z + acc.w)) * ATTN_SCALE;
        if (base + l >= ctx) sc = NEG_BIG;

        // online softmax (per warp)
        float tm = sc;
        #pragma unroll
        for (int off = 16; off > 0; off >>= 1)
            tm = fmaxf(tm, __shfl_xor_sync(0xFFFFFFFFu, tm, off));
        const float mnew  = fmaxf(m, tm);
        const float alpha = __expf(m - mnew);
        const float p     = __expf(sc - mnew);   // masked lanes underflow to 0
        float tsum = p;
        #pragma unroll
        for (int off = 16; off > 0; off >>= 1)
            tsum += __shfl_xor_sync(0xFFFFFFFFu, tsum, off);
        lsum = lsum * alpha + tsum;
        m = mnew;

        // ---- publish weights to smem (per-warp-private row), read as broadcast LDS.128
        __syncwarp();
        ps[w * TILE + l] = p;
        __syncwarp();

        // ---- accumulate O: lane l owns dims 4l..4l+3
        o.x *= alpha; o.y *= alpha; o.z *= alpha; o.w *= alpha;
        #pragma unroll
        for (int j = 0; j < 8; ++j) {
            const float4 pw = *(const float4*)&ps[w * TILE + j * 4];
            const uint2 v0 = *(const uint2*)&vt[(j * 4 + 0) * ROWB + l * 4];
            const uint2 v1 = *(const uint2*)&vt[(j * 4 + 1) * ROWB + l * 4];
            const uint2 v2 = *(const uint2*)&vt[(j * 4 + 2) * ROWB + l * 4];
            const uint2 v3 = *(const uint2*)&vt[(j * 4 + 3) * ROWB + l * 4];
            o.x += pw.x * bflo(v0.x); o.y += pw.x * bfhi(v0.x);
            o.z += pw.x * bflo(v0.y); o.w += pw.x * bfhi(v0.y);
            o.x += pw.y * bflo(v1.x); o.y += pw.y * bfhi(v1.x);
            o.z += pw.y * bflo(v1.y); o.w += pw.y * bfhi(v1.y);
            o.x += pw.z * bflo(v2.x); o.y += pw.z * bfhi(v2.x);
            o.z += pw.z * bflo(v2.y); o.w += pw.z * bfhi(v2.y);
            o.x += pw.w * bflo(v3.x); o.y += pw.w * bfhi(v3.x);
            o.z += pw.w * bflo(v3.y); o.w += pw.w * bfhi(v3.y);
        }
        __syncthreads();   // all warps done reading kt/vt of tile tb

        if (more) {
            CP_WAIT0();          // this thread's copies landed (only rows it converts)
            convert_tile(tb + 1);
            __syncthreads();     // conv tile tb+1 ready for all warps
        }
    }

    // ---- publish partials
    *(float4*)&g_po[s][h][split][w][l * 4] = o;
    if (l == 0) { g_pm[s][h][split][w] = m; g_pl[s][h][split][w] = lsum; }
    __threadfence();
    __syncthreads();

    // ---- last-CTA-per-(s,h) detection (threadFenceReduction pattern)
    if (t == 0) {
        const int old = atomicAdd(&g_cnt[s][h], 1);
        int last = (old == nsp - 1);
        if (last) g_cnt[s][h] = 0;     // restore for next graph replay (deterministic)
        *s_last = last;
    }
    __syncthreads();
    if (!*s_last) return;
    __threadfence();

    // ---- in-place combine for this (s,h): warp w = GQA sub-head, L2-resident reads
    const float mi = (l < nsp) ? g_pm[s][h][l][w] : NEG_BIG;
    const float li = (l < nsp) ? g_pl[s][h][l][w] : 0.f;
    float M = mi;
    #pragma unroll
    for (int off = 16; off > 0; off >>= 1)
        M = fmaxf(M, __shfl_xor_sync(0xFFFFFFFFu, M, off));
    const float wi = __expf(mi - M);     // 0 for inactive lanes
    float L = wi * li;
    #pragma unroll
    for (int off = 16; off > 0; off >>= 1)
        L += __shfl_xor_sync(0xFFFFFFFFu, L, off);

    float4 acc = make_float4(0.f, 0.f, 0.f, 0.f);
    #pragma unroll
    for (int i = 0; i < NSPLIT; ++i) {
        if (i < nsp) {
            const float wgt = __shfl_sync(0xFFFFFFFFu, wi, i);
            const float4 pv = *(const float4*)&g_po[s][h][i][w][l * 4];
            acc.x += wgt * pv.x; acc.y += wgt * pv.y;
            acc.z += wgt * pv.z; acc.w += wgt * pv.w;
        }
    }
    const float inv = 1.f / L;
    float4 r = make_float4(acc.x * inv, acc.y * inv, acc.z * inv, acc.w * inv);
    *(float4*)(out + (size_t)s * (NHEAD * HDIM)
                   + (size_t)(h * GQ + w) * HDIM + l * 4) = r;
}

extern "C" void kernel_launch(void* const* d_in, const int* in_sizes, int n_in,
                              void* d_out, int out_size) {
    (void)in_sizes; (void)n_in; (void)out_size;
    const float* q    = (const float*)d_in[0];
    const float* k    = (const float*)d_in[1];
    const float* v    = (const float*)d_in[2];
    const float* kc   = (const float*)d_in[3];
    const float* vc   = (const float*)d_in[4];
    const float* ksc  = (const float*)d_in[5];
    const float* vsc  = (const float*)d_in[6];
    // d_in[7] slot_mapping: unused (position ctx-1 substitution is equivalent)
    const int*   btab = (const int*)d_in[8];   // JAX x64 disabled -> int32
    const int*   clen = (const int*)d_in[9];

    cudaFuncSetAttribute(attn_fused_kernel,
                         cudaFuncAttributeMaxDynamicSharedMemorySize, SMEM_BYTES);
    dim3 g1(NSPLIT, NKVH, S_N);
    attn_fused_kernel<<<g1, 128, SMEM_BYTES>>>(q, k, v, kc, vc, ksc, vsc,
                                               btab, clen, (float*)d_out);
}

// round 13
// speedup vs baseline: 1.1881x; 1.0242x over previous
#include <cuda_runtime.h>
#include <cuda_fp8.h>
#include <cuda_bf16.h>

#define S_N     32
#define NHEAD   32
#define HDIM    128
#define NKVH    8
#define GQ      4
#define BSZ     16
#define MBLK    128
#define NSPLIT  16
#define CHUNK   128
#define TILE    32
#define ROWB    136          // bf16 elems per conv smem row (272B = 16B-aligned, conflict-free)
#define ATTN_SCALE 0.08838834764831845f
#define NEG_BIG   -3.402823466e38f

// dynamic smem layout (bytes)
#define OFF_RAWK  0
#define OFF_RAWV  (TILE * HDIM * 4)                        // 16384
#define OFF_KT    (OFF_RAWV + TILE * HDIM * 4)             // 32768
#define OFF_VT    (OFF_KT + TILE * ROWB * 2)               // +8704
#define OFF_QS    (OFF_VT + TILE * ROWB * 2)               // +8704
#define OFF_PT    (OFF_QS + GQ * HDIM * 4)                 // +2048  pt[TILE][GQ]
#define OFF_ALP   (OFF_PT + TILE * GQ * 4)                 // +512   alp[GQ]
#define OFF_LAST  (OFF_ALP + 16)
#define SMEM_BYTES (OFF_LAST + 16)                         // ~52.8 KB

// split-KV partial scratch (static device memory: allocation-free)
__device__ float g_po[S_N][NKVH][NSPLIT][GQ][HDIM];
__device__ float g_pm[S_N][NKVH][NSPLIT][GQ];
__device__ float g_pl[S_N][NKVH][NSPLIT][GQ];
__device__ int   g_cnt[S_N][NKVH];   // zero-init; protocol restores 0 every run

__device__ __forceinline__ void cp16(void* dst_smem, const void* src) {
    unsigned d = (unsigned)__cvta_generic_to_shared(dst_smem);
    asm volatile("cp.async.cg.shared.global [%0], [%1], 16;" :: "r"(d), "l"(src));
}
#define CP_COMMIT() asm volatile("cp.async.commit_group;" ::: "memory")
#define CP_WAIT0()  asm volatile("cp.async.wait_group 0;" ::: "memory")

// Exact emulation of reference dequant chain -> two packed bf16x2 words
__device__ __forceinline__ uint2 dq4_bf(float4 c, float s) {
    float2 a = make_float2(c.x, c.y);
    float2 b = make_float2(c.z, c.w);
    __nv_fp8x2_storage_t p0 = __nv_cvt_float2_to_fp8x2(a, __NV_SATFINITE, __NV_E4M3);
    __nv_fp8x2_storage_t p1 = __nv_cvt_float2_to_fp8x2(b, __NV_SATFINITE, __NV_E4M3);
    __half2_raw h0 = __nv_cvt_fp8x2_to_halfraw2(p0, __NV_E4M3);
    __half2_raw h1 = __nv_cvt_fp8x2_to_halfraw2(p1, __NV_E4M3);
    float2 f0 = __half22float2(*reinterpret_cast<__half2*>(&h0));
    float2 f1 = __half22float2(*reinterpret_cast<__half2*>(&h1));
    f0.x *= s; f0.y *= s; f1.x *= s; f1.y *= s;
    __nv_bfloat162 bb0 = __float22bfloat162_rn(f0);
    __nv_bfloat162 bb1 = __float22bfloat162_rn(f1);
    uint2 r;
    r.x = *reinterpret_cast<unsigned*>(&bb0);
    r.y = *reinterpret_cast<unsigned*>(&bb1);
    return r;
}

// bf16x2 word -> two exact f32 (bf16 value = upper 16 bits of f32)
__device__ __forceinline__ float bflo(unsigned u) { return __uint_as_float(u << 16); }
__device__ __forceinline__ float bfhi(unsigned u) { return __uint_as_float(u & 0xFFFF0000u); }

__global__ void __launch_bounds__(128)
attn_fused_kernel(const float* __restrict__ q, const float* __restrict__ knew,
                  const float* __restrict__ vnew, const float* __restrict__ kcache,
                  const float* __restrict__ vcache, const float* __restrict__ kscale_p,
                  const float* __restrict__ vscale_p, const int* __restrict__ btab,
                  const int* __restrict__ clen, float* __restrict__ out)
{
    extern __shared__ char smem[];
    float*          rawK = (float*)(smem + OFF_RAWK);          // [TILE][HDIM] f32
    float*          rawV = (float*)(smem + OFF_RAWV);
    unsigned short* kt   = (unsigned short*)(smem + OFF_KT);   // [TILE][ROWB] bf16
    unsigned short* vt   = (unsigned short*)(smem + OFF_VT);
    float*          qs   = (float*)(smem + OFF_QS);            // [GQ*HDIM]
    float*          pt   = (float*)(smem + OFF_PT);            // [TILE][GQ] weights
    float*          alp  = (float*)(smem + OFF_ALP);           // [GQ] alphas
    int*            s_last = (int*)(smem + OFF_LAST);

    const int split = blockIdx.x;
    const int h     = blockIdx.y;
    const int s     = blockIdx.z;
    const int ctx   = clen[s];
    const int c0    = split * CHUNK;
    const int nsp   = (ctx + CHUNK - 1) / CHUNK;   // active splits for this seq
    if (split >= nsp) return;
    const int nvalid = min(CHUNK, ctx - c0);
    const int ntile  = (nvalid + TILE - 1) / TILE;

    const int t = threadIdx.x;
    const int w = t >> 5;     // warp = query head within GQA group (QK/softmax)
    const int l = t & 31;     // lane

    // stage Q (512 floats, raw f32 as in reference)
    ((float4*)qs)[t] = ((const float4*)(q + (size_t)s * (NHEAD * HDIM)
                                          + (size_t)h * (GQ * HDIM)))[t];
    const float ks = kscale_p[h];
    const float vs = vscale_p[h];
    const float* kp = knew + (size_t)s * (NKVH * HDIM) + h * HDIM + l * 4;
    const float* vp = vnew + (size_t)s * (NKVH * HDIM) + h * HDIM + l * 4;

    // hoist the chunk's 8 cache-block indices (independent LDGs, once per CTA)
    unsigned blkArr[CHUNK / BSZ];
    #pragma unroll
    for (int j = 0; j < CHUNK / BSZ; ++j)
        blkArr[j] = (unsigned)btab[s * MBLK + (c0 >> 4) + j];

    // issue one tile's raw K/V into smem via cp.async (32-bit offsets: max 67M elems)
    auto issue_tile = [&](int tb) {
        const unsigned base = (unsigned)(c0 + (tb << 5));
        #pragma unroll
        for (int i = 0; i < 8; ++i) {
            const int pl = i * 4 + w;          // tile-local position 0..31
            const unsigned Pa = base + (unsigned)pl;   // global position (< 2048: safe)
            const unsigned roff = (blkArr[tb * 2 + (pl >> 4)] * BSZ + (Pa & 15u))
                                  * (unsigned)(NKVH * HDIM) + (unsigned)(h * HDIM + l * 4);
            cp16(&rawK[pl * HDIM + l * 4], kcache + roff);
            cp16(&rawV[pl * HDIM + l * 4], vcache + roff);
        }
        CP_COMMIT();
    };

    // dq-convert raw f32 tile -> bf16 conv tiles. Reads ONLY the rows this same
    // thread cp.async'd (same pl, same l*4) => thread-local CP_WAIT0 suffices.
    auto convert_tile = [&](int tb) {
        const int base = c0 + (tb << 5);
        #pragma unroll
        for (int i = 0; i < 8; ++i) {
            const int pl = i * 4 + w;
            float4 kv = *(const float4*)&rawK[pl * HDIM + l * 4];
            float4 vv = *(const float4*)&rawV[pl * HDIM + l * 4];
            if (base + pl == ctx - 1) {  // new token: reference scatters fp8(x/scale) here
                float4 kn4 = *(const float4*)kp;
                float4 vn4 = *(const float4*)vp;
                kv = make_float4(__fdiv_rn(kn4.x, ks), __fdiv_rn(kn4.y, ks),
                                 __fdiv_rn(kn4.z, ks), __fdiv_rn(kn4.w, ks));
                vv = make_float4(__fdiv_rn(vn4.x, vs), __fdiv_rn(vn4.y, vs),
                                 __fdiv_rn(vn4.z, vs), __fdiv_rn(vn4.w, vs));
            }
            *(uint2*)&kt[pl * ROWB + l * 4] = dq4_bf(kv, ks);
            *(uint2*)&vt[pl * ROWB + l * 4] = dq4_bf(vv, vs);
        }
    };

    float  m    = NEG_BIG;
    float  lsum = 0.f;
    // per-lane partial O: 4 heads x 4 dims (this warp's 8 V rows only)
    float4 oa0 = make_float4(0.f,0.f,0.f,0.f);
    float4 oa1 = make_float4(0.f,0.f,0.f,0.f);
    float4 oa2 = make_float4(0.f,0.f,0.f,0.f);
    float4 oa3 = make_float4(0.f,0.f,0.f,0.f);

    // prologue: stage tile 0
    issue_tile(0);
    CP_WAIT0();
    convert_tile(0);
    __syncthreads();

    for (int tb = 0; tb < ntile; ++tb) {
        const int base = c0 + (tb << 5);
        const bool more = (tb + 1 < ntile);

        // overlap: next tile's gmem->smem copies fly while we compute this tile
        if (more) issue_tile(tb + 1);

        // ---- scores: warp w = head w, lane l = position l (row l of K, 8 bf16 per LDS.128)
        float4 acc = make_float4(0.f, 0.f, 0.f, 0.f);
        #pragma unroll
        for (int d8 = 0; d8 < 16; ++d8) {
            const uint4  kq = *(const uint4*)&kt[l * ROWB + d8 * 8];
            const float4 qa = *(const float4*)&qs[w * HDIM + d8 * 8];
            const float4 qb = *(const float4*)&qs[w * HDIM + d8 * 8 + 4];
            acc.x += bflo(kq.x) * qa.x; acc.y += bfhi(kq.x) * qa.y;
            acc.z += bflo(kq.y) * qa.z; acc.w += bfhi(kq.y) * qa.w;
            acc.x += bflo(kq.z) * qb.x; acc.y += bfhi(kq.z) * qb.y;
            acc.z += bflo(kq.w) * qb.z; acc.w += bfhi(kq.w) * qb.w;
        }
        float sc = ((acc.x + acc.y) + (acc.z + acc.w)) * ATTN_SCALE;
        if (base + l >= ctx) sc = NEG_BIG;

        // online softmax (per warp = head w)
        float tm = sc;
        #pragma unroll
        for (int off = 16; off > 0; off >>= 1)
            tm = fmaxf(tm, __shfl_xor_sync(0xFFFFFFFFu, tm, off));
        const float mnew  = fmaxf(m, tm);
        const float alpha = __expf(m - mnew);
        const float p     = __expf(sc - mnew);   // masked lanes underflow to 0
        float tsum = p;
        #pragma unroll
        for (int off = 16; off > 0; off >>= 1)
            tsum += __shfl_xor_sync(0xFFFFFFFFu, tsum, off);
        lsum = lsum * alpha + tsum;
        m = mnew;

        // ---- publish weights transposed: pt[row l][head w]; alphas per head
        pt[l * GQ + w] = p;
        if (l == 0) alp[w] = alpha;
        __syncthreads();      // all heads' weights visible to all warps

        // ---- PV (head-deduplicated): warp w covers V rows 8w..8w+7 for ALL 4 heads.
        //      lane l owns dims 4l..4l+3: V word loaded+unpacked ONCE, used x4 heads.
        {
            const float4 av = *(const float4*)alp;     // broadcast: 4 alphas
            oa0.x*=av.x; oa0.y*=av.x; oa0.z*=av.x; oa0.w*=av.x;
            oa1.x*=av.y; oa1.y*=av.y; oa1.z*=av.y; oa1.w*=av.y;
            oa2.x*=av.z; oa2.y*=av.z; oa2.z*=av.z; oa2.w*=av.z;
            oa3.x*=av.w; oa3.y*=av.w; oa3.z*=av.w; oa3.w*=av.w;
            #pragma unroll
            for (int j = 0; j < 8; ++j) {
                const int r = w * 8 + j;
                const uint2  vq = *(const uint2*)&vt[r * ROWB + l * 4];   // this lane's dims
                const float4 pr = *(const float4*)&pt[r * GQ];            // 4 heads' weights
                const float v0 = bflo(vq.x), v1 = bfhi(vq.x);
                const float v2 = bflo(vq.y), v3 = bfhi(vq.y);
                oa0.x += pr.x*v0; oa0.y += pr.x*v1; oa0.z += pr.x*v2; oa0.w += pr.x*v3;
                oa1.x += pr.y*v0; oa1.y += pr.y*v1; oa1.z += pr.y*v2; oa1.w += pr.y*v3;
                oa2.x += pr.z*v0; oa2.y += pr.z*v1; oa2.z += pr.z*v2; oa2.w += pr.z*v3;
                oa3.x += pr.w*v0; oa3.y += pr.w*v1; oa3.z += pr.w*v2; oa3.w += pr.w*v3;
            }
        }
        __syncthreads();   // all warps done reading kt/vt/pt of tile tb

        if (more) {
            CP_WAIT0();          // this thread's copies landed (only rows it converts)
            convert_tile(tb + 1);
            __syncthreads();     // conv tile tb+1 ready for all warps
        }
    }

    // ---- cross-warp O reduction: rawK is dead -> scratch [src warp][head][128 dims]
    {
        float* red = rawK;
        *(float4*)&red[(w * GQ + 0) * HDIM + l * 4] = oa0;
        *(float4*)&red[(w * GQ + 1) * HDIM + l * 4] = oa1;
        *(float4*)&red[(w * GQ + 2) * HDIM + l * 4] = oa2;
        *(float4*)&red[(w * GQ + 3) * HDIM + l * 4] = oa3;
        __syncthreads();
        // warp w = head w gathers its head across the 4 source warps
        float4 o = make_float4(0.f,0.f,0.f,0.f);
        #pragma unroll
        for (int sw = 0; sw < 4; ++sw) {
            const float4 pv = *(const float4*)&red[(sw * GQ + w) * HDIM + l * 4];
            o.x += pv.x; o.y += pv.y; o.z += pv.z; o.w += pv.w;
        }
        *(float4*)&g_po[s][h][split][w][l * 4] = o;
    }
    if (l == 0) { g_pm[s][h][split][w] = m; g_pl[s][h][split][w] = lsum; }
    __threadfence();
    __syncthreads();

    // ---- last-CTA-per-(s,h) detection (threadFenceReduction pattern)
    if (t == 0) {
        const int old = atomicAdd(&g_cnt[s][h], 1);
        int last = (old == nsp - 1);
        if (last) g_cnt[s][h] = 0;     // restore for next graph replay (deterministic)
        *s_last = last;
    }
    __syncthreads();
    if (!*s_last) return;
    __threadfence();

    // ---- in-place combine for this (s,h): warp w = GQA sub-head, L2-resident reads
    const float mi = (l < nsp) ? g_pm[s][h][l][w] : NEG_BIG;
    const float li = (l < nsp) ? g_pl[s][h][l][w] : 0.f;
    float M = mi;
    #pragma unroll
    for (int off = 16; off > 0; off >>= 1)
        M = fmaxf(M, __shfl_xor_sync(0xFFFFFFFFu, M, off));
    const float wi = __expf(mi - M);     // 0 for inactive lanes
    float L = wi * li;
    #pragma unroll
    for (int off = 16; off > 0; off >>= 1)
        L += __shfl_xor_sync(0xFFFFFFFFu, L, off);

    float4 acc = make_float4(0.f, 0.f, 0.f, 0.f);
    #pragma unroll
    for (int i = 0; i < NSPLIT; ++i) {
        if (i < nsp) {
            const float wgt = __shfl_sync(0xFFFFFFFFu, wi, i);
            const float4 pv = *(const float4*)&g_po[s][h][i][w][l * 4];
            acc.x += wgt * pv.x; acc.y += wgt * pv.y;
            acc.z += wgt * pv.z; acc.w += wgt * pv.w;
        }
    }
    const float inv = 1.f / L;
    float4 r = make_float4(acc.x * inv, acc.y * inv, acc.z * inv, acc.w * inv);
    *(float4*)(out + (size_t)s * (NHEAD * HDIM)
                   + (size_t)(h * GQ + w) * HDIM + l * 4) = r;
}

extern "C" void kernel_launch(void* const* d_in, const int* in_sizes, int n_in,
                              void* d_out, int out_size) {
    (void)in_sizes; (void)n_in; (void)out_size;
    const float* q    = (const float*)d_in[0];
    const float* k    = (const float*)d_in[1];
    const float* v    = (const float*)d_in[2];
    const float* kc   = (const float*)d_in[3];
    const float* vc   = (const float*)d_in[4];
    const float* ksc  = (const float*)d_in[5];
    const float* vsc  = (const float*)d_in[6];
    // d_in[7] slot_mapping: unused (position ctx-1 substitution is equivalent)
    const int*   btab = (const int*)d_in[8];   // JAX x64 disabled -> int32
    const int*   clen = (const int*)d_in[9];

    cudaFuncSetAttribute(attn_fused_kernel,
                         cudaFuncAttributeMaxDynamicSharedMemorySize, SMEM_BYTES);
    dim3 g1(NSPLIT, NKVH, S_N);
    attn_fused_kernel<<<g1, 128, SMEM_BYTES>>>(q, k, v, kc, vc, ksc, vsc,
                                               btab, clen, (float*)d_out);
}